// round 11
// baseline (speedup 1.0000x reference)
#include <cuda_runtime.h>
#include <cuda_bf16.h>
#include <cstdint>

#define HID     32
#define TILE_M  128
#define THREADS 256
#define BSTRIDE 136                  // padded bf16 per B row (272B): conflict-free ldmatrix
#define BHALF   (64 * BSTRIDE)       // elements per version (hi/lo)

#define APITCH   96                  // bytes per A row in smem stage
#define ASTAGE   (32 * APITCH)       // 3072 B per stage per pair
#define ADEPTH   3
#define NPAIR    4
#define ARING    (NPAIR * ADEPTH * ASTAGE)    // 36864
#define SB_OFF   ARING
#define SRED_OFF (ARING + 2 * BHALF * 2)      // + 34816 = 71680
#define SMEM_DYN (SRED_OFF + 2 * TILE_M * 4)  // + 1024 = 72704

// Fused W^T, split bf16, gate-interleaved rows:
// storage row n: b=n>>3, i=n&7; gate=b&1 (0:z,1:h); col j=(b>>1)*8+i.
// Rows [0..31]: z0-7,h0-7,z8-15,h8-15 (n-half 0); rows [32..63]: j=16..31 (n-half 1).
__device__ __align__(16) __nv_bfloat16 g_B[2 * BHALF];

// W tensors shape (2,1,160,32); [s,0,k,j] = s*5120 + k*32 + j; only k<128 live (H0=0).
__global__ void prep_kernel(const float* __restrict__ Wz, const float* __restrict__ Wh) {
    int idx = blockIdx.x * blockDim.x + threadIdx.x;   // 0..8191
    if (idx >= 64 * 128) return;
    int n = idx >> 7;
    int k = idx & 127;
    int b = n >> 3;
    int i = n & 7;
    int j = (b >> 1) * 8 + i;
    const float* W = (b & 1) ? Wh : Wz;
    float v = W[k * 32 + j] + W[5120 + k * 32 + j];
    __nv_bfloat16 hi = __float2bfloat16_rn(v);
    float lo = v - __bfloat162float(hi);
    g_B[n * BSTRIDE + k]         = hi;
    g_B[BHALF + n * BSTRIDE + k] = __float2bfloat16_rn(lo);
}

// ---------------- helpers ----------------
__device__ __forceinline__ uint32_t smem_u32(const void* p) {
    uint32_t a;
    asm("{ .reg .u64 t; cvta.to.shared.u64 t, %1; cvt.u32.u64 %0, t; }" : "=r"(a) : "l"(p));
    return a;
}
__device__ __forceinline__ void mma_bf16(float* d, const uint32_t* a, const uint32_t* b) {
    asm volatile(
        "mma.sync.aligned.m16n8k16.row.col.f32.bf16.bf16.f32 "
        "{%0,%1,%2,%3}, {%4,%5,%6,%7}, {%8,%9}, {%0,%1,%2,%3};"
        : "+f"(d[0]), "+f"(d[1]), "+f"(d[2]), "+f"(d[3])
        : "r"(a[0]), "r"(a[1]), "r"(a[2]), "r"(a[3]), "r"(b[0]), "r"(b[1]));
}
__device__ __forceinline__ void ldm_x4(uint32_t* r, uint32_t addr) {
    asm volatile("ldmatrix.sync.aligned.m8n8.x4.shared.b16 {%0,%1,%2,%3}, [%4];"
        : "=r"(r[0]), "=r"(r[1]), "=r"(r[2]), "=r"(r[3]) : "r"(addr));
}
__device__ __forceinline__ void cpasync16(uint32_t dst, const void* src) {
    asm volatile("cp.async.cg.shared.global [%0], [%1], 16;" :: "r"(dst), "l"(src));
}
__device__ __forceinline__ void cp_commit() {
    asm volatile("cp.async.commit_group;" ::: "memory");
}
__device__ __forceinline__ void cp_wait2() {
    asm volatile("cp.async.wait_group 2;" ::: "memory");
}
__device__ __forceinline__ void pair_bar(int id) {
    asm volatile("bar.sync %0, 64;" :: "r"(id) : "memory");
}
__device__ __forceinline__ uint32_t pack_bf2(float a, float b) {
    __nv_bfloat162 t = __floats2bfloat162_rn(a, b);
    return *(uint32_t*)&t;
}
__device__ __forceinline__ float sigmoid_f(float v) {
    return __fdividef(1.0f, 1.0f + __expf(-v));
}
__device__ __forceinline__ float tanh_f(float v) {
    return 1.0f - __fdividef(2.0f, __expf(2.0f * v) + 1.0f);
}

__global__ void __launch_bounds__(THREADS, 3)
dcrnn_mma_kernel(const float* __restrict__ x,
                 const float* __restrict__ bz, const float* __restrict__ bh,
                 const float* __restrict__ wlin, const float* __restrict__ blin,
                 float* __restrict__ out, int nNodes)
{
    extern __shared__ __align__(16) unsigned char dsm[];
    __nv_bfloat16* sB   = (__nv_bfloat16*)(dsm + SB_OFF);
    float*         sRed = (float*)(dsm + SRED_OFF);

    const int tid  = threadIdx.x;
    const int warp = tid >> 5;
    const int lane = tid & 31;
    const int pair  = warp >> 1;       // 0..3, owns 32 rows
    const int nhalf = warp & 1;        // B storage-row half (cols j: nhalf*16..+16)
    const int g = lane >> 2;           // 0..7
    const int c = lane & 3;            // 0..3
    const int rowBase = blockIdx.x * TILE_M + pair * 32;

    // ---- producer mapping: 64 threads of a pair fill one 32x64B stage ----
    const int ptid = tid & 63;
    const int prow = ptid & 31;        // row in stage
    const int pch  = (ptid >> 5) * 2;  // 16B-chunk pair: warp0 -> 0,1; warp1 -> 2,3
    int growp = rowBase + prow;
    if (growp >= nNodes) growp = nNodes - 1;
    const float* srcRow = x + (size_t)growp * 128 + pch * 4;

    const uint32_t pairRing = smem_u32(dsm) + (uint32_t)(pair * ADEPTH * ASTAGE);
    const uint32_t dstTb    = (uint32_t)(prow * APITCH + pch * 16);

    auto issueA = [&](int kt, int st) {
        uint32_t d0 = pairRing + (uint32_t)(st * ASTAGE) + dstTb;
        const float* s = srcRow + kt * 16;
        cpasync16(d0,      s);
        cpasync16(d0 + 16, s + 4);
    };

    // prologue: stages 0,1,2 <- kt 0,1,2 (before B staging to overlap DRAM)
    issueA(0, 0); cp_commit();
    issueA(1, 1); cp_commit();
    issueA(2, 2); cp_commit();

    // stage B (hi+lo) -> smem, 2176 uint4
    {
        const uint4* src = (const uint4*)g_B;
        uint4*       dst = (uint4*)sB;
        #pragma unroll
        for (int i = 0; i < 2176 / THREADS + 1; i++) {
            int e = tid + i * THREADS;
            if (e < 2176) dst[e] = src[e];
        }
    }
    __syncthreads();

    // B ldmatrix per-thread address (within this warp's 32 storage rows):
    const uint32_t sB0 = smem_u32(sB);
    const uint32_t tb  = (uint32_t)((((lane >> 4) << 3) + (lane & 7)) * (BSTRIDE * 2)
                                    + ((lane >> 3) & 1) * 16);
    const uint32_t bbase = sB0 + (uint32_t)(nhalf * 32 * BSTRIDE * 2) + tb;

    // acc[mt][nt][e]: nt even = z block, nt odd = h block (same cols)
    float acc[2][4][4];
    #pragma unroll
    for (int mt = 0; mt < 2; mt++)
        #pragma unroll
        for (int nt = 0; nt < 4; nt++)
            #pragma unroll
            for (int e = 0; e < 4; e++) acc[mt][nt][e] = 0.0f;

    int scur = 0;
    #pragma unroll 1
    for (int kt = 0; kt < 8; kt++) {
        cp_wait2();                    // this thread's group kt is complete
        pair_bar(pair + 1);            // both warps' halves visible

        // consume stage scur: LDS.64 fragments + hi/lo split in regs
        unsigned char* stp = dsm + pair * ADEPTH * ASTAGE + scur * ASTAGE;
        uint32_t Ah[2][4], Al[2][4];
        #pragma unroll
        for (int mt = 0; mt < 2; mt++) {
            int r0 = g + 16 * mt;
            int r1 = g + 8 + 16 * mt;
            float2 f0 = *(const float2*)(stp + r0 * APITCH + 8 * c);
            float2 f1 = *(const float2*)(stp + r1 * APITCH + 8 * c);
            float2 f2 = *(const float2*)(stp + r0 * APITCH + 32 + 8 * c);
            float2 f3 = *(const float2*)(stp + r1 * APITCH + 32 + 8 * c);
            float2 fv[4] = {f0, f1, f2, f3};
            #pragma unroll
            for (int q = 0; q < 4; q++) {
                __nv_bfloat162 h2 = __floats2bfloat162_rn(fv[q].x, fv[q].y);
                float lx = fv[q].x - __bfloat162float(h2.x);
                float ly = fv[q].y - __bfloat162float(h2.y);
                Ah[mt][q] = *(uint32_t*)&h2;
                Al[mt][q] = pack_bf2(lx, ly);
            }
        }
        pair_bar(pair + 1);            // all reads of scur done before refill
        if (kt + 3 < 8) issueA(kt + 3, scur);
        cp_commit();                   // uniform group counting

        // B hi fragments: 2x ldmatrix.x4 -> this warp's 4 n-tiles
        uint32_t B2[4][2];
        #pragma unroll
        for (int p = 0; p < 2; p++) {
            uint32_t r4[4];
            ldm_x4(r4, bbase + p * (16 * BSTRIDE * 2) + kt * 32);
            B2[2 * p][0] = r4[0];     B2[2 * p][1] = r4[1];
            B2[2 * p + 1][0] = r4[2]; B2[2 * p + 1][1] = r4[3];
        }
        #pragma unroll
        for (int mt = 0; mt < 2; mt++)
            #pragma unroll
            for (int nt = 0; nt < 4; nt++)
                mma_bf16(acc[mt][nt], Ah[mt], B2[nt]);     // xh * wh
        #pragma unroll
        for (int mt = 0; mt < 2; mt++)
            #pragma unroll
            for (int nt = 0; nt < 4; nt++)
                mma_bf16(acc[mt][nt], Al[mt], B2[nt]);     // xl * wh

        // B lo fragments (reuse regs)
        #pragma unroll
        for (int p = 0; p < 2; p++) {
            uint32_t r4[4];
            ldm_x4(r4, bbase + 2 * BHALF + p * (16 * BSTRIDE * 2) + kt * 32);
            B2[2 * p][0] = r4[0];     B2[2 * p][1] = r4[1];
            B2[2 * p + 1][0] = r4[2]; B2[2 * p + 1][1] = r4[3];
        }
        #pragma unroll
        for (int mt = 0; mt < 2; mt++)
            #pragma unroll
            for (int nt = 0; nt < 4; nt++)
                mma_bf16(acc[mt][nt], Ah[mt], B2[nt]);     // xh * wl

        scur = (scur == ADEPTH - 1) ? 0 : scur + 1;
    }

    // ---- epilogue: nt pairs (0,1)=(z,h) j=nhalf*16+2c+e, (2,3)=+8.
    //      Post-nonlinearity W_lin partials are linear -> summable across n-halves.
    #pragma unroll
    for (int r = 0; r < 4; r++) {
        int mt = r >> 1;
        int eb = (r & 1) * 2;          // c0/c1 = row g, c2/c3 = row g+8
        float partial = 0.0f;
        #pragma unroll
        for (int p = 0; p < 2; p++) {
            #pragma unroll
            for (int e = 0; e < 2; e++) {
                int j = nhalf * 16 + p * 8 + 2 * c + e;
                float zv = acc[mt][2 * p][eb + e]     + __ldg(bz + j);
                float hv = acc[mt][2 * p + 1][eb + e] + __ldg(bh + j);
                float zz = sigmoid_f(zv);
                float ht = tanh_f(hv);
                partial = fmaf(fmaxf((1.0f - zz) * ht, 0.0f), __ldg(wlin + j), partial);
            }
        }
        partial += __shfl_xor_sync(0xffffffffu, partial, 1);
        partial += __shfl_xor_sync(0xffffffffu, partial, 2);
        if (c == 0) sRed[nhalf * TILE_M + pair * 32 + g + 8 * r] = partial;
    }
    __syncthreads();

    if (tid < TILE_M) {
        int grow = blockIdx.x * TILE_M + tid;
        if (grow < nNodes)
            out[grow] = sRed[tid] + sRed[TILE_M + tid] + __ldg(blin);
    }
}

// Inputs (metadata order):
// 0:x[N*128] f32   1:edge_index (dead)   2:edge_weight (dead)
// 3:W_z[10240]     4:b_z[32]   5:W_r (dead)   6:b_r (dead)
// 7:W_h[10240]     8:b_h[32]   9:W_lin[32]   10:b_lin[1]
extern "C" void kernel_launch(void* const* d_in, const int* in_sizes, int n_in,
                              void* d_out, int out_size) {
    const float* x     = (const float*)d_in[0];
    const float* W_z   = (const float*)d_in[3];
    const float* b_z   = (const float*)d_in[4];
    const float* W_h   = (const float*)d_in[7];
    const float* b_h   = (const float*)d_in[8];
    const float* W_lin = (const float*)d_in[9];
    const float* b_lin = (const float*)d_in[10];
    float* out = (float*)d_out;

    int nNodes = out_size;

    // Idempotent, every call (no static guards per harness rules)
    cudaFuncSetAttribute(dcrnn_mma_kernel,
                         cudaFuncAttributeMaxDynamicSharedMemorySize, SMEM_DYN);

    prep_kernel<<<(64 * 128 + 255) / 256, 256>>>(W_z, W_h);
    int blocks = (nNodes + TILE_M - 1) / TILE_M;
    dcrnn_mma_kernel<<<blocks, THREADS, SMEM_DYN>>>(x, b_z, b_h, W_lin, b_lin,
                                                    out, nNodes);
}

// round 12
// speedup vs baseline: 1.2317x; 1.2317x over previous
#include <cuda_runtime.h>
#include <cuda_bf16.h>
#include <cstdint>

#define HID     32
#define TILE_M  256
#define THREADS 256
#define BSTRIDE 136                  // padded bf16 per B row (272B): conflict-free ldmatrix
#define BHALF   (64 * BSTRIDE)       // elements per version (hi/lo)

#define APITCH   64                  // bytes per A row in smem ring (16 f32, no pad)
#define ASTAGE   (32 * APITCH)       // 2048 B per stage per warp
#define ADEPTH   4
#define ARING    (8 * ADEPTH * ASTAGE)       // 65536 B
#define SB_OFF   ARING
#define SMEM_DYN (ARING + 2 * BHALF * 2)     // + 34816 B = 100352

// Fused W^T, split bf16: [hi: 64 rows x 136][lo: same], row n = output col, k contiguous.
__device__ __align__(16) __nv_bfloat16 g_B[2 * BHALF];

// W tensors shape (2,1,160,32); [s,0,k,j] = s*5120 + k*32 + j; only k<128 live (H0=0).
// B[n][k]: n<32 -> z gate col n, n>=32 -> h gate col n-32.
__global__ void prep_kernel(const float* __restrict__ Wz, const float* __restrict__ Wh) {
    int idx = blockIdx.x * blockDim.x + threadIdx.x;   // 0..8191
    if (idx >= 64 * 128) return;
    int n = idx >> 7;
    int k = idx & 127;
    int j = n & 31;
    const float* W = (n < 32) ? Wz : Wh;
    float v = W[k * 32 + j] + W[5120 + k * 32 + j];
    __nv_bfloat16 hi = __float2bfloat16_rn(v);
    float lo = v - __bfloat162float(hi);
    g_B[n * BSTRIDE + k]         = hi;
    g_B[BHALF + n * BSTRIDE + k] = __float2bfloat16_rn(lo);
}

// ---------------- helpers ----------------
__device__ __forceinline__ uint32_t smem_u32(const void* p) {
    uint32_t a;
    asm("{ .reg .u64 t; cvta.to.shared.u64 t, %1; cvt.u32.u64 %0, t; }" : "=r"(a) : "l"(p));
    return a;
}
__device__ __forceinline__ void mma_bf16(float* d, const uint32_t* a, const uint32_t* b) {
    asm volatile(
        "mma.sync.aligned.m16n8k16.row.col.f32.bf16.bf16.f32 "
        "{%0,%1,%2,%3}, {%4,%5,%6,%7}, {%8,%9}, {%0,%1,%2,%3};"
        : "+f"(d[0]), "+f"(d[1]), "+f"(d[2]), "+f"(d[3])
        : "r"(a[0]), "r"(a[1]), "r"(a[2]), "r"(a[3]), "r"(b[0]), "r"(b[1]));
}
__device__ __forceinline__ void ldm_x4(uint32_t* r, uint32_t addr) {
    asm volatile("ldmatrix.sync.aligned.m8n8.x4.shared.b16 {%0,%1,%2,%3}, [%4];"
        : "=r"(r[0]), "=r"(r[1]), "=r"(r[2]), "=r"(r[3]) : "r"(addr));
}
__device__ __forceinline__ void cpasync16(uint32_t dst, const void* src) {
    asm volatile("cp.async.cg.shared.global [%0], [%1], 16;" :: "r"(dst), "l"(src));
}
__device__ __forceinline__ void cp_commit() {
    asm volatile("cp.async.commit_group;" ::: "memory");
}
__device__ __forceinline__ void cp_wait3() {
    asm volatile("cp.async.wait_group 3;" ::: "memory");
}
__device__ __forceinline__ uint32_t pack_bf2(float a, float b) {
    __nv_bfloat162 t = __floats2bfloat162_rn(a, b);
    return *(uint32_t*)&t;
}
__device__ __forceinline__ float sigmoid_f(float v) {
    return __fdividef(1.0f, 1.0f + __expf(-v));
}
__device__ __forceinline__ float tanh_f(float v) {
    return 1.0f - __fdividef(2.0f, __expf(2.0f * v) + 1.0f);
}

__global__ void __launch_bounds__(THREADS, 2)
dcrnn_mma_kernel(const float* __restrict__ x,
                 const float* __restrict__ bz, const float* __restrict__ bh,
                 const float* __restrict__ wlin, const float* __restrict__ blin,
                 float* __restrict__ out, int nNodes)
{
    extern __shared__ __align__(16) unsigned char dsm[];
    unsigned char* smA = dsm;                 // A ring: warp w stage s at (w*ADEPTH+s)*ASTAGE
    __nv_bfloat16*  sB = (__nv_bfloat16*)(dsm + SB_OFF);

    const int tid = threadIdx.x;
    const int warp = tid >> 5;
    const int lane = tid & 31;
    const int g    = lane >> 2;        // 0..7
    const int c    = lane & 3;         // 0..3
    const int r8   = lane >> 2;        // async row-in-octet
    const int ch   = lane & 3;         // async 16B chunk
    const int rowBase = blockIdx.x * TILE_M + warp * 32;

    const uint32_t warpRing = smem_u32(smA) + (uint32_t)(warp * ADEPTH * ASTAGE);

    // ---- async producer: stage 'st' <- A rows for k-tile kt ----
    auto issueA = [&](int kt, int st) {
        uint32_t dstBase = warpRing + (uint32_t)(st * ASTAGE);
        #pragma unroll
        for (int j = 0; j < 4; j++) {
            int lrow = j * 8 + r8;
            int grow = rowBase + lrow;
            if (grow >= nNodes) grow = nNodes - 1;
            const void* src = x + (size_t)grow * 128 + kt * 16 + ch * 4;
            cpasync16(dstBase + (uint32_t)(lrow * APITCH + ch * 16), src);
        }
    };

    // prologue: stages 0..3 <- kt 0..3 (prefetch distance 3 in steady state)
    issueA(0, 0); cp_commit();
    issueA(1, 1); cp_commit();
    issueA(2, 2); cp_commit();
    issueA(3, 3); cp_commit();

    // stage B (hi+lo) -> smem, 2176 uint4
    {
        const uint4* src = (const uint4*)g_B;
        uint4*       dst = (uint4*)sB;
        #pragma unroll
        for (int i = 0; i < 2176 / THREADS + 1; i++) {
            int e = tid + i * THREADS;
            if (e < 2176) dst[e] = src[e];
        }
    }
    __syncthreads();

    // B ldmatrix per-thread address component:
    const uint32_t sB0 = smem_u32(sB);
    const uint32_t tb  = (uint32_t)((((lane >> 4) << 3) + (lane & 7)) * (BSTRIDE * 2)
                                    + ((lane >> 3) & 1) * 16);
    const uint32_t bbase = sB0 + tb;

    float acc[2][8][4];
    #pragma unroll
    for (int mt = 0; mt < 2; mt++)
        #pragma unroll
        for (int nt = 0; nt < 8; nt++)
            #pragma unroll
            for (int e = 0; e < 4; e++) acc[mt][nt][e] = 0.0f;

    int scur = 0;
    #pragma unroll 1
    for (int kt = 0; kt < 8; kt++) {
        // B hi fragments first — independent of the A pipeline, complete during wait
        uint32_t B2[8][2];
        #pragma unroll
        for (int p = 0; p < 8; p += 2) {
            uint32_t r4[4];
            ldm_x4(r4, bbase + p * (8 * BSTRIDE * 2) + kt * 32);
            B2[p][0] = r4[0]; B2[p][1] = r4[1];
            B2[p + 1][0] = r4[2]; B2[p + 1][1] = r4[3];
        }

        cp_wait3();              // group kt complete (<=3 pending)
        __syncwarp();

        // consume stage scur: fragment LDS.64 + hi/lo split in regs
        unsigned char* stp = smA + warp * ADEPTH * ASTAGE + scur * ASTAGE;
        uint32_t Ah[2][4], Al[2][4];
        #pragma unroll
        for (int mt = 0; mt < 2; mt++) {
            int r0 = g + 16 * mt;
            int r1 = g + 8 + 16 * mt;
            float2 f0 = *(const float2*)(stp + r0 * APITCH + 8 * c);        // cols 2c,2c+1
            float2 f1 = *(const float2*)(stp + r1 * APITCH + 8 * c);
            float2 f2 = *(const float2*)(stp + r0 * APITCH + 32 + 8 * c);   // cols 8+2c
            float2 f3 = *(const float2*)(stp + r1 * APITCH + 32 + 8 * c);
            float2 fv[4] = {f0, f1, f2, f3};
            #pragma unroll
            for (int q = 0; q < 4; q++) {
                __nv_bfloat162 h2 = __floats2bfloat162_rn(fv[q].x, fv[q].y);
                float lx = fv[q].x - __bfloat162float(h2.x);
                float ly = fv[q].y - __bfloat162float(h2.y);
                Ah[mt][q] = *(uint32_t*)&h2;
                Al[mt][q] = pack_bf2(lx, ly);
            }
        }

        // refill: stage scur <- kt+4
        if (kt + 4 < 8) issueA(kt + 4, scur);
        cp_commit();             // uniform group counting

        #pragma unroll
        for (int mt = 0; mt < 2; mt++)
            #pragma unroll
            for (int nt = 0; nt < 8; nt++)
                mma_bf16(acc[mt][nt], Ah[mt], B2[nt]);     // xh * wh
        #pragma unroll
        for (int mt = 0; mt < 2; mt++)
            #pragma unroll
            for (int nt = 0; nt < 8; nt++)
                mma_bf16(acc[mt][nt], Al[mt], B2[nt]);     // xl * wh

        // B lo fragments (reuse regs)
        #pragma unroll
        for (int p = 0; p < 8; p += 2) {
            uint32_t r4[4];
            ldm_x4(r4, bbase + 2 * BHALF + p * (8 * BSTRIDE * 2) + kt * 32);
            B2[p][0] = r4[0]; B2[p][1] = r4[1];
            B2[p + 1][0] = r4[2]; B2[p + 1][1] = r4[3];
        }
        #pragma unroll
        for (int mt = 0; mt < 2; mt++)
            #pragma unroll
            for (int nt = 0; nt < 8; nt++)
                mma_bf16(acc[mt][nt], Ah[mt], B2[nt]);     // xh * wl

        scur = (scur + 1) & (ADEPTH - 1);
    }

    // ---- epilogue: z at col j (n-tiles 0..3), h at col j+32 (n-tiles 4..7),
    //      both owned by the same thread. Quad shfl-reduce, lane c==0 stores.
    float bl = __ldg(blin);
    #pragma unroll
    for (int r = 0; r < 4; r++) {
        int mt = r >> 1;
        int eb = (r & 1) * 2;          // c0/c1 = row g, c2/c3 = row g+8
        float partial = 0.0f;
        #pragma unroll
        for (int ntz = 0; ntz < 4; ntz++) {
            #pragma unroll
            for (int e = 0; e < 2; e++) {
                int j = ntz * 8 + 2 * c + e;
                float zv = acc[mt][ntz][eb + e]     + __ldg(bz + j);
                float hv = acc[mt][ntz + 4][eb + e] + __ldg(bh + j);
                float zz = sigmoid_f(zv);
                float ht = tanh_f(hv);
                partial = fmaf(fmaxf((1.0f - zz) * ht, 0.0f), __ldg(wlin + j), partial);
            }
        }
        partial += __shfl_xor_sync(0xffffffffu, partial, 1);
        partial += __shfl_xor_sync(0xffffffffu, partial, 2);
        if (c == 0) {
            int grow = rowBase + g + 8 * r;
            if (grow < nNodes) out[grow] = partial + bl;
        }
    }
}

// Inputs (metadata order):
// 0:x[N*128] f32   1:edge_index (dead)   2:edge_weight (dead)
// 3:W_z[10240]     4:b_z[32]   5:W_r (dead)   6:b_r (dead)
// 7:W_h[10240]     8:b_h[32]   9:W_lin[32]   10:b_lin[1]
extern "C" void kernel_launch(void* const* d_in, const int* in_sizes, int n_in,
                              void* d_out, int out_size) {
    const float* x     = (const float*)d_in[0];
    const float* W_z   = (const float*)d_in[3];
    const float* b_z   = (const float*)d_in[4];
    const float* W_h   = (const float*)d_in[7];
    const float* b_h   = (const float*)d_in[8];
    const float* W_lin = (const float*)d_in[9];
    const float* b_lin = (const float*)d_in[10];
    float* out = (float*)d_out;

    int nNodes = out_size;

    // Idempotent, every call (no static guards per harness rules)
    cudaFuncSetAttribute(dcrnn_mma_kernel,
                         cudaFuncAttributeMaxDynamicSharedMemorySize, SMEM_DYN);

    prep_kernel<<<(64 * 128 + 255) / 256, 256>>>(W_z, W_h);
    int blocks = (nNodes + TILE_M - 1) / TILE_M;
    dcrnn_mma_kernel<<<blocks, THREADS, SMEM_DYN>>>(x, b_z, b_h, W_lin, b_lin,
                                                    out, nNodes);
}

// round 13
// speedup vs baseline: 1.2429x; 1.0091x over previous
#include <cuda_runtime.h>
#include <cuda_bf16.h>
#include <cstdint>

#define HID     32
#define TILE_M  256
#define THREADS 256
#define BSTRIDE 136                  // padded bf16 per B row (272B): conflict-free ldmatrix
#define BHALF   (64 * BSTRIDE)       // elements per version (hi/lo)

#define APITCH   80                  // bytes per A row: (20r+2c)%32 bank-perm, 16B-aligned
#define ASTAGE   (32 * APITCH)       // 2560 B per stage per warp
#define ADEPTH   3
#define ARING    (8 * ADEPTH * ASTAGE)       // 61440 B
#define SB_OFF   ARING
#define SMEM_DYN (ARING + 2 * BHALF * 2)     // + 34816 B = 96256

// Fused W^T, split bf16: [hi: 64 rows x 136][lo: same], row n = output col, k contiguous.
__device__ __align__(16) __nv_bfloat16 g_B[2 * BHALF];

// W tensors shape (2,1,160,32); [s,0,k,j] = s*5120 + k*32 + j; only k<128 live (H0=0).
// B[n][k]: n<32 -> z gate col n, n>=32 -> h gate col n-32.
__global__ void prep_kernel(const float* __restrict__ Wz, const float* __restrict__ Wh) {
    int idx = blockIdx.x * blockDim.x + threadIdx.x;   // 0..8191
    if (idx >= 64 * 128) return;
    int n = idx >> 7;
    int k = idx & 127;
    int j = n & 31;
    const float* W = (n < 32) ? Wz : Wh;
    float v = W[k * 32 + j] + W[5120 + k * 32 + j];
    __nv_bfloat16 hi = __float2bfloat16_rn(v);
    float lo = v - __bfloat162float(hi);
    g_B[n * BSTRIDE + k]         = hi;
    g_B[BHALF + n * BSTRIDE + k] = __float2bfloat16_rn(lo);
}

// ---------------- helpers ----------------
__device__ __forceinline__ uint32_t smem_u32(const void* p) {
    uint32_t a;
    asm("{ .reg .u64 t; cvta.to.shared.u64 t, %1; cvt.u32.u64 %0, t; }" : "=r"(a) : "l"(p));
    return a;
}
__device__ __forceinline__ void mma_bf16(float* d, const uint32_t* a, const uint32_t* b) {
    asm volatile(
        "mma.sync.aligned.m16n8k16.row.col.f32.bf16.bf16.f32 "
        "{%0,%1,%2,%3}, {%4,%5,%6,%7}, {%8,%9}, {%0,%1,%2,%3};"
        : "+f"(d[0]), "+f"(d[1]), "+f"(d[2]), "+f"(d[3])
        : "r"(a[0]), "r"(a[1]), "r"(a[2]), "r"(a[3]), "r"(b[0]), "r"(b[1]));
}
__device__ __forceinline__ void ldm_x4(uint32_t* r, uint32_t addr) {
    asm volatile("ldmatrix.sync.aligned.m8n8.x4.shared.b16 {%0,%1,%2,%3}, [%4];"
        : "=r"(r[0]), "=r"(r[1]), "=r"(r[2]), "=r"(r[3]) : "r"(addr));
}
__device__ __forceinline__ void cpasync16(uint32_t dst, const void* src) {
    asm volatile("cp.async.cg.shared.global [%0], [%1], 16;" :: "r"(dst), "l"(src));
}
__device__ __forceinline__ void cp_commit() {
    asm volatile("cp.async.commit_group;" ::: "memory");
}
__device__ __forceinline__ void cp_wait2() {
    asm volatile("cp.async.wait_group 2;" ::: "memory");
}
__device__ __forceinline__ uint32_t pack_bf2(float a, float b) {
    __nv_bfloat162 t = __floats2bfloat162_rn(a, b);
    return *(uint32_t*)&t;
}
__device__ __forceinline__ float sigmoid_f(float v) {
    return __fdividef(1.0f, 1.0f + __expf(-v));
}
__device__ __forceinline__ float tanh_f(float v) {
    return 1.0f - __fdividef(2.0f, __expf(2.0f * v) + 1.0f);
}

__global__ void __launch_bounds__(THREADS, 2)
dcrnn_mma_kernel(const float* __restrict__ x,
                 const float* __restrict__ bz, const float* __restrict__ bh,
                 const float* __restrict__ wlin, const float* __restrict__ blin,
                 float* __restrict__ out, int nNodes)
{
    extern __shared__ __align__(16) unsigned char dsm[];
    unsigned char* smA = dsm;                 // A ring: warp w stage s at (w*ADEPTH+s)*ASTAGE
    __nv_bfloat16*  sB = (__nv_bfloat16*)(dsm + SB_OFF);

    const int tid = threadIdx.x;
    const int warp = tid >> 5;
    const int lane = tid & 31;
    const int g    = lane >> 2;        // 0..7
    const int c    = lane & 3;         // 0..3
    const int r8   = lane >> 2;        // async row-in-octet
    const int ch   = lane & 3;         // async 16B chunk
    const int rowBase = blockIdx.x * TILE_M + warp * 32;

    const uint32_t warpRing = smem_u32(smA) + (uint32_t)(warp * ADEPTH * ASTAGE);

    // ---- async producer: stage 'st' <- A rows for k-tile kt ----
    auto issueA = [&](int kt, int st) {
        uint32_t dstBase = warpRing + (uint32_t)(st * ASTAGE);
        #pragma unroll
        for (int j = 0; j < 4; j++) {
            int lrow = j * 8 + r8;
            int grow = rowBase + lrow;
            if (grow >= nNodes) grow = nNodes - 1;
            const void* src = x + (size_t)grow * 128 + kt * 16 + ch * 4;
            cpasync16(dstBase + (uint32_t)(lrow * APITCH + ch * 16), src);
        }
    };

    // prologue: stages 0,1,2 <- kt 0,1,2
    issueA(0, 0); cp_commit();
    issueA(1, 1); cp_commit();
    issueA(2, 2); cp_commit();

    // stage B (hi+lo) -> smem, 2176 uint4
    {
        const uint4* src = (const uint4*)g_B;
        uint4*       dst = (uint4*)sB;
        #pragma unroll
        for (int i = 0; i < 2176 / THREADS + 1; i++) {
            int e = tid + i * THREADS;
            if (e < 2176) dst[e] = src[e];
        }
    }
    __syncthreads();

    // B ldmatrix per-thread address component:
    const uint32_t sB0 = smem_u32(sB);
    const uint32_t tb  = (uint32_t)((((lane >> 4) << 3) + (lane & 7)) * (BSTRIDE * 2)
                                    + ((lane >> 3) & 1) * 16);
    const uint32_t bbase = sB0 + tb;

    float acc[2][8][4];
    #pragma unroll
    for (int mt = 0; mt < 2; mt++)
        #pragma unroll
        for (int nt = 0; nt < 8; nt++)
            #pragma unroll
            for (int e = 0; e < 4; e++) acc[mt][nt][e] = 0.0f;

    #pragma unroll
    for (int kt = 0; kt < 8; kt++) {
        const int scur = kt % ADEPTH;

        cp_wait2();              // group kt complete (<=2 pending)
        __syncwarp();

        // consume stage scur: fragment LDS.64 (bank-permutation pitch) + hi/lo split
        unsigned char* stp = smA + warp * ADEPTH * ASTAGE + scur * ASTAGE;
        uint32_t Ah[2][4], Al[2][4];
        #pragma unroll
        for (int mt = 0; mt < 2; mt++) {
            int r0 = g + 16 * mt;
            int r1 = g + 8 + 16 * mt;
            float2 f0 = *(const float2*)(stp + r0 * APITCH + 8 * c);        // cols 2c,2c+1
            float2 f1 = *(const float2*)(stp + r1 * APITCH + 8 * c);
            float2 f2 = *(const float2*)(stp + r0 * APITCH + 32 + 8 * c);   // cols 8+2c
            float2 f3 = *(const float2*)(stp + r1 * APITCH + 32 + 8 * c);
            float2 fv[4] = {f0, f1, f2, f3};
            #pragma unroll
            for (int q = 0; q < 4; q++) {
                __nv_bfloat162 h2 = __floats2bfloat162_rn(fv[q].x, fv[q].y);
                float lx = fv[q].x - __bfloat162float(h2.x);
                float ly = fv[q].y - __bfloat162float(h2.y);
                Ah[mt][q] = *(uint32_t*)&h2;
                Al[mt][q] = pack_bf2(lx, ly);
            }
        }

        // refill: stage scur <- kt+3
        if (kt + 3 < 8) issueA(kt + 3, scur);
        cp_commit();             // uniform group counting

        // B fragments interleaved per n-pair: hi+lo issued together, 12 MMAs per pair.
        // Per-acc accumulation order (hi, xl*wh, xh*wl per kt) matches prior rounds.
        #pragma unroll
        for (int q = 0; q < 4; q++) {
            uint32_t Bhi[4], Blo[4];
            ldm_x4(Bhi, bbase + q * (16 * BSTRIDE * 2) + kt * 32);
            ldm_x4(Blo, bbase + 2 * BHALF + q * (16 * BSTRIDE * 2) + kt * 32);
            #pragma unroll
            for (int mt = 0; mt < 2; mt++) {
                mma_bf16(acc[mt][2 * q + 0], Ah[mt], Bhi + 0);   // xh * wh
                mma_bf16(acc[mt][2 * q + 0], Al[mt], Bhi + 0);   // xl * wh
                mma_bf16(acc[mt][2 * q + 0], Ah[mt], Blo + 0);   // xh * wl
                mma_bf16(acc[mt][2 * q + 1], Ah[mt], Bhi + 2);
                mma_bf16(acc[mt][2 * q + 1], Al[mt], Bhi + 2);
                mma_bf16(acc[mt][2 * q + 1], Ah[mt], Blo + 2);
            }
        }
    }

    // ---- epilogue: z at col j (n-tiles 0..3), h at col j+32 (n-tiles 4..7),
    //      both owned by the same thread. Quad shfl-reduce, lane c==0 stores.
    float bl = __ldg(blin);
    #pragma unroll
    for (int r = 0; r < 4; r++) {
        int mt = r >> 1;
        int eb = (r & 1) * 2;          // c0/c1 = row g, c2/c3 = row g+8
        float partial = 0.0f;
        #pragma unroll
        for (int ntz = 0; ntz < 4; ntz++) {
            #pragma unroll
            for (int e = 0; e < 2; e++) {
                int j = ntz * 8 + 2 * c + e;
                float zv = acc[mt][ntz][eb + e]     + __ldg(bz + j);
                float hv = acc[mt][ntz + 4][eb + e] + __ldg(bh + j);
                float zz = sigmoid_f(zv);
                float ht = tanh_f(hv);
                partial = fmaf(fmaxf((1.0f - zz) * ht, 0.0f), __ldg(wlin + j), partial);
            }
        }
        partial += __shfl_xor_sync(0xffffffffu, partial, 1);
        partial += __shfl_xor_sync(0xffffffffu, partial, 2);
        if (c == 0) {
            int grow = rowBase + g + 8 * r;
            if (grow < nNodes) out[grow] = partial + bl;
        }
    }
}

// Inputs (metadata order):
// 0:x[N*128] f32   1:edge_index (dead)   2:edge_weight (dead)
// 3:W_z[10240]     4:b_z[32]   5:W_r (dead)   6:b_r (dead)
// 7:W_h[10240]     8:b_h[32]   9:W_lin[32]   10:b_lin[1]
extern "C" void kernel_launch(void* const* d_in, const int* in_sizes, int n_in,
                              void* d_out, int out_size) {
    const float* x     = (const float*)d_in[0];
    const float* W_z   = (const float*)d_in[3];
    const float* b_z   = (const float*)d_in[4];
    const float* W_h   = (const float*)d_in[7];
    const float* b_h   = (const float*)d_in[8];
    const float* W_lin = (const float*)d_in[9];
    const float* b_lin = (const float*)d_in[10];
    float* out = (float*)d_out;

    int nNodes = out_size;

    // Idempotent, every call (no static guards per harness rules)
    cudaFuncSetAttribute(dcrnn_mma_kernel,
                         cudaFuncAttributeMaxDynamicSharedMemorySize, SMEM_DYN);

    prep_kernel<<<(64 * 128 + 255) / 256, 256>>>(W_z, W_h);
    int blocks = (nNodes + TILE_M - 1) / TILE_M;
    dcrnn_mma_kernel<<<blocks, THREADS, SMEM_DYN>>>(x, b_z, b_h, W_lin, b_lin,
                                                    out, nNodes);
}

// round 14
// speedup vs baseline: 1.2493x; 1.0052x over previous
#include <cuda_runtime.h>
#include <cuda_bf16.h>
#include <cstdint>

#define HID     32
#define TILE_M  256
#define THREADS 256
#define BSTRIDE 136                  // padded bf16 per B row (272B): conflict-free ldmatrix
#define BHALF   (64 * BSTRIDE)       // elements per version (hi/lo)

#define APITCH   80                  // bytes per A row: bank-permutation, 16B-aligned
#define ASTAGE   (32 * APITCH)       // 2560 B per stage per warp
#define ADEPTH   3
#define ARING    (8 * ADEPTH * ASTAGE)       // 61440 B
#define SB_OFF   ARING
#define SMEM_DYN (ARING + 2 * BHALF * 2)     // + 34816 B = 96256

// ---------------- helpers ----------------
__device__ __forceinline__ uint32_t smem_u32(const void* p) {
    uint32_t a;
    asm("{ .reg .u64 t; cvta.to.shared.u64 t, %1; cvt.u32.u64 %0, t; }" : "=r"(a) : "l"(p));
    return a;
}
__device__ __forceinline__ void mma_bf16(float* d, const uint32_t* a, const uint32_t* b) {
    asm volatile(
        "mma.sync.aligned.m16n8k16.row.col.f32.bf16.bf16.f32 "
        "{%0,%1,%2,%3}, {%4,%5,%6,%7}, {%8,%9}, {%0,%1,%2,%3};"
        : "+f"(d[0]), "+f"(d[1]), "+f"(d[2]), "+f"(d[3])
        : "r"(a[0]), "r"(a[1]), "r"(a[2]), "r"(a[3]), "r"(b[0]), "r"(b[1]));
}
__device__ __forceinline__ void ldm_x4(uint32_t* r, uint32_t addr) {
    asm volatile("ldmatrix.sync.aligned.m8n8.x4.shared.b16 {%0,%1,%2,%3}, [%4];"
        : "=r"(r[0]), "=r"(r[1]), "=r"(r[2]), "=r"(r[3]) : "r"(addr));
}
__device__ __forceinline__ void cpasync16(uint32_t dst, const void* src) {
    asm volatile("cp.async.cg.shared.global [%0], [%1], 16;" :: "r"(dst), "l"(src));
}
__device__ __forceinline__ void cp_commit() {
    asm volatile("cp.async.commit_group;" ::: "memory");
}
__device__ __forceinline__ void cp_wait2() {
    asm volatile("cp.async.wait_group 2;" ::: "memory");
}
__device__ __forceinline__ uint32_t pack_bf2(float a, float b) {
    __nv_bfloat162 t = __floats2bfloat162_rn(a, b);
    return *(uint32_t*)&t;
}
__device__ __forceinline__ float sigmoid_f(float v) {
    return __fdividef(1.0f, 1.0f + __expf(-v));
}
__device__ __forceinline__ float tanh_f(float v) {
    return 1.0f - __fdividef(2.0f, __expf(2.0f * v) + 1.0f);
}

__global__ void __launch_bounds__(THREADS, 2)
dcrnn_mma_kernel(const float* __restrict__ x,
                 const float* __restrict__ Wz, const float* __restrict__ Wh,
                 const float* __restrict__ bz, const float* __restrict__ bh,
                 const float* __restrict__ wlin, const float* __restrict__ blin,
                 float* __restrict__ out, int nNodes)
{
    extern __shared__ __align__(16) unsigned char dsm[];
    unsigned char* smA = dsm;                 // A ring: warp w stage s at (w*ADEPTH+s)*ASTAGE
    __nv_bfloat16*  sB = (__nv_bfloat16*)(dsm + SB_OFF);

    const int tid = threadIdx.x;
    const int warp = tid >> 5;
    const int lane = tid & 31;
    const int g    = lane >> 2;        // 0..7
    const int c    = lane & 3;         // 0..3
    const int r8   = lane >> 2;        // async row-in-octet
    const int ch   = lane & 3;         // async 16B chunk
    const int rowBase = blockIdx.x * TILE_M + warp * 32;

    const uint32_t warpRing = smem_u32(smA) + (uint32_t)(warp * ADEPTH * ASTAGE);

    // ---- async producer: stage 'st' <- A rows for k-tile kt ----
    auto issueA = [&](int kt, int st) {
        uint32_t dstBase = warpRing + (uint32_t)(st * ASTAGE);
        #pragma unroll
        for (int j = 0; j < 4; j++) {
            int lrow = j * 8 + r8;
            int grow = rowBase + lrow;
            if (grow >= nNodes) grow = nNodes - 1;
            const void* src = x + (size_t)grow * 128 + kt * 16 + ch * 4;
            cpasync16(dstBase + (uint32_t)(lrow * APITCH + ch * 16), src);
        }
    };

    // prologue: stages 0,1,2 <- kt 0,1,2 (DRAM traffic in flight during B prep below)
    issueA(0, 0); cp_commit();
    issueA(1, 1); cp_commit();
    issueA(2, 2); cp_commit();

    // ---- fused B prep: build split-bf16 W^T tiles directly from W_z/W_h ----
    // W tensors shape (2,1,160,32); [s,0,k,j] = s*5120 + k*32 + j; only k<128 live (H0=0).
    // sB row n (n<32: z col n, n>=32: h col n-32), col k. Coalesced: thread lane = j.
    {
        const int j  = tid & 31;              // gate column (coalesced across lanes)
        const int k0 = (tid >> 5) * 16;       // 16-k slab per warp
        #pragma unroll
        for (int kk = 0; kk < 16; kk++) {
            int k = k0 + kk;
            float vz = Wz[k * 32 + j] + Wz[5120 + k * 32 + j];
            float vh = Wh[k * 32 + j] + Wh[5120 + k * 32 + j];
            __nv_bfloat16 zh = __float2bfloat16_rn(vz);
            __nv_bfloat16 hh = __float2bfloat16_rn(vh);
            sB[j * BSTRIDE + k]                  = zh;
            sB[(j + 32) * BSTRIDE + k]           = hh;
            sB[BHALF + j * BSTRIDE + k]          = __float2bfloat16_rn(vz - __bfloat162float(zh));
            sB[BHALF + (j + 32) * BSTRIDE + k]   = __float2bfloat16_rn(vh - __bfloat162float(hh));
        }
    }
    __syncthreads();

    // B ldmatrix per-thread address component:
    const uint32_t sB0 = smem_u32(sB);
    const uint32_t tb  = (uint32_t)((((lane >> 4) << 3) + (lane & 7)) * (BSTRIDE * 2)
                                    + ((lane >> 3) & 1) * 16);
    const uint32_t bbase = sB0 + tb;

    float acc[2][8][4];
    #pragma unroll
    for (int mt = 0; mt < 2; mt++)
        #pragma unroll
        for (int nt = 0; nt < 8; nt++)
            #pragma unroll
            for (int e = 0; e < 4; e++) acc[mt][nt][e] = 0.0f;

    #pragma unroll
    for (int kt = 0; kt < 8; kt++) {
        const int scur = kt % ADEPTH;

        cp_wait2();              // group kt complete (<=2 pending)
        __syncwarp();

        // consume stage scur: fragment LDS.64 (bank-permutation pitch) + hi/lo split
        unsigned char* stp = smA + warp * ADEPTH * ASTAGE + scur * ASTAGE;
        uint32_t Ah[2][4], Al[2][4];
        #pragma unroll
        for (int mt = 0; mt < 2; mt++) {
            int r0 = g + 16 * mt;
            int r1 = g + 8 + 16 * mt;
            float2 f0 = *(const float2*)(stp + r0 * APITCH + 8 * c);        // cols 2c,2c+1
            float2 f1 = *(const float2*)(stp + r1 * APITCH + 8 * c);
            float2 f2 = *(const float2*)(stp + r0 * APITCH + 32 + 8 * c);   // cols 8+2c
            float2 f3 = *(const float2*)(stp + r1 * APITCH + 32 + 8 * c);
            float2 fv[4] = {f0, f1, f2, f3};
            #pragma unroll
            for (int q = 0; q < 4; q++) {
                __nv_bfloat162 h2 = __floats2bfloat162_rn(fv[q].x, fv[q].y);
                float lx = fv[q].x - __bfloat162float(h2.x);
                float ly = fv[q].y - __bfloat162float(h2.y);
                Ah[mt][q] = *(uint32_t*)&h2;
                Al[mt][q] = pack_bf2(lx, ly);
            }
        }

        // refill: stage scur <- kt+3
        if (kt + 3 < 8) issueA(kt + 3, scur);
        cp_commit();             // uniform group counting

        // B fragments interleaved per n-pair: hi+lo issued together, 12 MMAs per pair.
        #pragma unroll
        for (int q = 0; q < 4; q++) {
            uint32_t Bhi[4], Blo[4];
            ldm_x4(Bhi, bbase + q * (16 * BSTRIDE * 2) + kt * 32);
            ldm_x4(Blo, bbase + 2 * BHALF + q * (16 * BSTRIDE * 2) + kt * 32);
            #pragma unroll
            for (int mt = 0; mt < 2; mt++) {
                mma_bf16(acc[mt][2 * q + 0], Ah[mt], Bhi + 0);   // xh * wh
                mma_bf16(acc[mt][2 * q + 0], Al[mt], Bhi + 0);   // xl * wh
                mma_bf16(acc[mt][2 * q + 0], Ah[mt], Blo + 0);   // xh * wl
                mma_bf16(acc[mt][2 * q + 1], Ah[mt], Bhi + 2);
                mma_bf16(acc[mt][2 * q + 1], Al[mt], Bhi + 2);
                mma_bf16(acc[mt][2 * q + 1], Ah[mt], Blo + 2);
            }
        }
    }

    // ---- epilogue: z at col j (n-tiles 0..3), h at col j+32 (n-tiles 4..7),
    //      both owned by the same thread. Quad shfl-reduce, lane c==0 stores.
    float bl = __ldg(blin);
    #pragma unroll
    for (int r = 0; r < 4; r++) {
        int mt = r >> 1;
        int eb = (r & 1) * 2;          // c0/c1 = row g, c2/c3 = row g+8
        float partial = 0.0f;
        #pragma unroll
        for (int ntz = 0; ntz < 4; ntz++) {
            #pragma unroll
            for (int e = 0; e < 2; e++) {
                int j = ntz * 8 + 2 * c + e;
                float zv = acc[mt][ntz][eb + e]     + __ldg(bz + j);
                float hv = acc[mt][ntz + 4][eb + e] + __ldg(bh + j);
                float zz = sigmoid_f(zv);
                float ht = tanh_f(hv);
                partial = fmaf(fmaxf((1.0f - zz) * ht, 0.0f), __ldg(wlin + j), partial);
            }
        }
        partial += __shfl_xor_sync(0xffffffffu, partial, 1);
        partial += __shfl_xor_sync(0xffffffffu, partial, 2);
        if (c == 0) {
            int grow = rowBase + g + 8 * r;
            if (grow < nNodes) out[grow] = partial + bl;
        }
    }
}

// Inputs (metadata order):
// 0:x[N*128] f32   1:edge_index (dead)   2:edge_weight (dead)
// 3:W_z[10240]     4:b_z[32]   5:W_r (dead)   6:b_r (dead)
// 7:W_h[10240]     8:b_h[32]   9:W_lin[32]   10:b_lin[1]
extern "C" void kernel_launch(void* const* d_in, const int* in_sizes, int n_in,
                              void* d_out, int out_size) {
    const float* x     = (const float*)d_in[0];
    const float* W_z   = (const float*)d_in[3];
    const float* b_z   = (const float*)d_in[4];
    const float* W_h   = (const float*)d_in[7];
    const float* b_h   = (const float*)d_in[8];
    const float* W_lin = (const float*)d_in[9];
    const float* b_lin = (const float*)d_in[10];
    float* out = (float*)d_out;

    int nNodes = out_size;

    // Idempotent, every call (no static guards per harness rules)
    cudaFuncSetAttribute(dcrnn_mma_kernel,
                         cudaFuncAttributeMaxDynamicSharedMemorySize, SMEM_DYN);

    int blocks = (nNodes + TILE_M - 1) / TILE_M;
    dcrnn_mma_kernel<<<blocks, THREADS, SMEM_DYN>>>(x, W_z, W_h, b_z, b_h,
                                                    W_lin, b_lin, out, nNodes);
}